// round 9
// baseline (speedup 1.0000x reference)
#include <cuda_runtime.h>
#include <cuda_fp16.h>
#include <cuda_bf16.h>
#include <math.h>
#include <stdint.h>

#define NN 50000
#define EE 800000
#define DD 64
#define BR 128   // rows per GEMM block (8 warps x 16 rows)
#define CAP 96   // per-warp smem stash (max in-degree safety; Poisson(16))
#define NB ((NN + 255) / 256)   // 196 scan blocks

// ---------------- device scratch (static, no allocation) ----------------
__device__ int   g_flag;
__device__ int   g_cnt[NN];
__device__ int   g_rowptr[NN + 1];
__device__ int   g_fill[NN];
__device__ int   g_bsum[256];            // per-block scan sums (NB <= 256)
__device__ unsigned short g_srcs16[EE];
__device__ __align__(16) unsigned short g_xh[NN * DD];     // x hi (bf16 bits)
__device__ __align__(16) unsigned short g_xl[NN * DD];     // x lo (bf16 bits)
__device__ __align__(16) unsigned short g_Wh[8 * DD * DD]; // W^T hi, 8 slots
__device__ __align__(16) unsigned short g_Wl[8 * DD * DD]; // W^T lo
__device__ __align__(16) __half g_hh[NN * DD];             // per-conv h (fp16)
__device__ float g_ssrc[NN];
__device__ float g_sdst[NN];

__device__ __forceinline__ void split_bf16(float v, unsigned short& hi, unsigned short& lo) {
    __nv_bfloat16 h = __float2bfloat16(v);
    float r = v - __bfloat162float(h);
    __nv_bfloat16 l = __float2bfloat16(r);
    hi = *reinterpret_cast<unsigned short*>(&h);
    lo = *reinterpret_cast<unsigned short*>(&l);
}

// ---------------- launch 0: init (detect + zero + cvt feat + cvt W) -----
__global__ void k_init(const int* __restrict__ raw,
                       const float* __restrict__ feat,
                       const float* __restrict__ W1,
                       const float* __restrict__ W2) {
    int i = blockIdx.x * blockDim.x + threadIdx.x;
    if (i < NN * DD) split_bf16(feat[i], g_xh[i], g_xl[i]);
    if (i < NN) g_cnt[i] = 0;
    if (i < 8 * DD * DD) {
        int g = i >> 12;
        int idx = i & 4095;
        int k = idx >> 6, c = idx & 63;
        const float* W = (g < 4) ? W1 : W2;
        float v = W[(g & 3) * DD * DD + k * DD + c];
        split_bf16(v, g_Wh[g * DD * DD + c * DD + k], g_Wl[g * DD * DD + c * DD + k]);
    }
    if (blockIdx.x == 0) {
        __shared__ int ok;
        if (threadIdx.x == 0) ok = 1;
        __syncthreads();
        for (int j = threadIdx.x; j < 4096; j += blockDim.x)
            if (raw[2 * j + 1] != 0) ok = 0;
        __syncthreads();
        if (threadIdx.x == 0) g_flag = ok;
    }
}

// ---------------- histogram of dst ----------------
__global__ void k_hist(const void* __restrict__ raw, int E) {
    int base = (blockIdx.x * blockDim.x + threadIdx.x) * 4;
    if (g_flag) {
        const long long* p = (const long long*)raw + E;
#pragma unroll
        for (int u = 0; u < 4; u++) { int j = base + u; if (j < E) atomicAdd(&g_cnt[(int)p[j]], 1); }
    } else {
        const int* p = (const int*)raw + E;
#pragma unroll
        for (int u = 0; u < 4; u++) { int j = base + u; if (j < E) atomicAdd(&g_cnt[p[j]], 1); }
    }
}

// ---------------- 3-phase parallel scan ----------------
// Phase A: block-local scan; local-exclusive into g_rowptr, block sum out.
__global__ void k_scanA() {
    __shared__ int sh[256];
    int t = threadIdx.x;
    int i = blockIdx.x * 256 + t;
    int v = (i < NN) ? g_cnt[i] : 0;
    sh[t] = v;
    __syncthreads();
#pragma unroll
    for (int off = 1; off < 256; off <<= 1) {
        int u = (t >= off) ? sh[t - off] : 0;
        __syncthreads();
        sh[t] += u;
        __syncthreads();
    }
    if (i <= NN && i < (blockIdx.x + 1) * 256)
        if (i < NN) g_rowptr[i] = sh[t] - v;     // local exclusive
    if (t == 255) g_bsum[blockIdx.x] = sh[255];
}

// Phase B: single block scans the NB block sums -> exclusive offsets.
__global__ void k_scanB() {
    __shared__ int sh[256];
    int t = threadIdx.x;
    int v = (t < NB) ? g_bsum[t] : 0;
    sh[t] = v;
    __syncthreads();
#pragma unroll
    for (int off = 1; off < 256; off <<= 1) {
        int u = (t >= off) ? sh[t - off] : 0;
        __syncthreads();
        sh[t] += u;
        __syncthreads();
    }
    if (t < NB) g_bsum[t] = sh[t] - v;           // exclusive
}

// Phase C: add block offsets; populate rowptr + fill; cap rowptr[NN]=E.
__global__ void k_scanC(int E) {
    int i = blockIdx.x * 256 + threadIdx.x;
    if (i < NN) {
        int r = g_rowptr[i] + g_bsum[blockIdx.x];
        g_rowptr[i] = r;
        g_fill[i] = r;
    }
    if (i == 0) g_rowptr[NN] = E;
}

// ---------------- scatter into CSR ----------------
__global__ void k_scatter(const void* __restrict__ raw, int E) {
    int base = (blockIdx.x * blockDim.x + threadIdx.x) * 4;
    if (g_flag) {
        const long long* p = (const long long*)raw;
#pragma unroll
        for (int u = 0; u < 4; u++) {
            int j = base + u;
            if (j < E) {
                int pos = atomicAdd(&g_fill[(int)p[E + j]], 1);
                g_srcs16[pos] = (unsigned short)(int)p[j];
            }
        }
    } else {
        const int* p = (const int*)raw;
#pragma unroll
        for (int u = 0; u < 4; u++) {
            int j = base + u;
            if (j < E) {
                int pos = atomicAdd(&g_fill[p[E + j]], 1);
                g_srcs16[pos] = (unsigned short)p[j];
            }
        }
    }
}

// ---------------- tensor-core GEMM (8 warps, dynamic smem) --------------
__global__ void __launch_bounds__(256) k_gemm(
        int g, const float* __restrict__ a_s, const float* __restrict__ a_d) {
    extern __shared__ __align__(16) char smem[];
    unsigned short (*Ah)[72] = (unsigned short(*)[72])(smem);
    unsigned short (*Al)[72] = (unsigned short(*)[72])(smem + 18432);
    unsigned short (*Bh)[72] = (unsigned short(*)[72])(smem + 36864);
    unsigned short (*Bl)[72] = (unsigned short(*)[72])(smem + 46080);
    int t = threadIdx.x;
    int rb = blockIdx.x * BR;

    for (int i = t; i < 512; i += 256) {
        int c = i >> 3, q = i & 7;
        ((uint4*)&Bh[c][0])[q] = ((const uint4*)(g_Wh + g * DD * DD + c * DD))[q];
        ((uint4*)&Bl[c][0])[q] = ((const uint4*)(g_Wl + g * DD * DD + c * DD))[q];
    }
    for (int i = t; i < 1024; i += 256) {
        int r = i >> 3, q = i & 7;
        int gr = rb + r; if (gr >= NN) gr = 0;
        ((uint4*)&Ah[r][0])[q] = ((const uint4*)(g_xh + (size_t)gr * DD))[q];
        ((uint4*)&Al[r][0])[q] = ((const uint4*)(g_xl + (size_t)gr * DD))[q];
    }
    __syncthreads();

    int lane = t & 31, wid = t >> 5;
    int gid = lane >> 2, tig = lane & 3;

    float acc[8][4];
#pragma unroll
    for (int nt = 0; nt < 8; nt++)
#pragma unroll
        for (int q = 0; q < 4; q++) acc[nt][q] = 0.f;

#pragma unroll
    for (int ks = 0; ks < 4; ks++) {
        int k0 = ks * 16 + 2 * tig;
        int r0 = wid * 16 + gid;
        uint32_t ahi[4], alo[4];
        ahi[0] = *(const uint32_t*)&Ah[r0][k0];
        ahi[1] = *(const uint32_t*)&Ah[r0 + 8][k0];
        ahi[2] = *(const uint32_t*)&Ah[r0][k0 + 8];
        ahi[3] = *(const uint32_t*)&Ah[r0 + 8][k0 + 8];
        alo[0] = *(const uint32_t*)&Al[r0][k0];
        alo[1] = *(const uint32_t*)&Al[r0 + 8][k0];
        alo[2] = *(const uint32_t*)&Al[r0][k0 + 8];
        alo[3] = *(const uint32_t*)&Al[r0 + 8][k0 + 8];
#pragma unroll
        for (int nt = 0; nt < 8; nt++) {
            int n = nt * 8 + gid;
            uint32_t bhi[2], blo[2];
            bhi[0] = *(const uint32_t*)&Bh[n][k0];
            bhi[1] = *(const uint32_t*)&Bh[n][k0 + 8];
            blo[0] = *(const uint32_t*)&Bl[n][k0];
            blo[1] = *(const uint32_t*)&Bl[n][k0 + 8];
            asm volatile(
                "mma.sync.aligned.m16n8k16.row.col.f32.bf16.bf16.f32 "
                "{%0,%1,%2,%3}, {%4,%5,%6,%7}, {%8,%9}, {%0,%1,%2,%3};"
                : "+f"(acc[nt][0]), "+f"(acc[nt][1]), "+f"(acc[nt][2]), "+f"(acc[nt][3])
                : "r"(ahi[0]), "r"(ahi[1]), "r"(ahi[2]), "r"(ahi[3]),
                  "r"(bhi[0]), "r"(bhi[1]));
            asm volatile(
                "mma.sync.aligned.m16n8k16.row.col.f32.bf16.bf16.f32 "
                "{%0,%1,%2,%3}, {%4,%5,%6,%7}, {%8,%9}, {%0,%1,%2,%3};"
                : "+f"(acc[nt][0]), "+f"(acc[nt][1]), "+f"(acc[nt][2]), "+f"(acc[nt][3])
                : "r"(ahi[0]), "r"(ahi[1]), "r"(ahi[2]), "r"(ahi[3]),
                  "r"(blo[0]), "r"(blo[1]));
            asm volatile(
                "mma.sync.aligned.m16n8k16.row.col.f32.bf16.bf16.f32 "
                "{%0,%1,%2,%3}, {%4,%5,%6,%7}, {%8,%9}, {%0,%1,%2,%3};"
                : "+f"(acc[nt][0]), "+f"(acc[nt][1]), "+f"(acc[nt][2]), "+f"(acc[nt][3])
                : "r"(alo[0]), "r"(alo[1]), "r"(alo[2]), "r"(alo[3]),
                  "r"(bhi[0]), "r"(bhi[1]));
        }
    }

    float2 asv[8], adv[8];
#pragma unroll
    for (int nt = 0; nt < 8; nt++) {
        asv[nt] = ((const float2*)a_s)[nt * 4 + tig];
        adv[nt] = ((const float2*)a_d)[nt * 4 + tig];
    }
    int r0 = rb + wid * 16 + gid;
    float ss0 = 0.f, sd0 = 0.f, ss1 = 0.f, sd1 = 0.f;
#pragma unroll
    for (int nt = 0; nt < 8; nt++) {
        ss0 = fmaf(acc[nt][0], asv[nt].x, fmaf(acc[nt][1], asv[nt].y, ss0));
        sd0 = fmaf(acc[nt][0], adv[nt].x, fmaf(acc[nt][1], adv[nt].y, sd0));
        ss1 = fmaf(acc[nt][2], asv[nt].x, fmaf(acc[nt][3], asv[nt].y, ss1));
        sd1 = fmaf(acc[nt][2], adv[nt].x, fmaf(acc[nt][3], adv[nt].y, sd1));
    }
#pragma unroll
    for (int o = 1; o <= 2; o <<= 1) {
        ss0 += __shfl_xor_sync(0xffffffffu, ss0, o);
        sd0 += __shfl_xor_sync(0xffffffffu, sd0, o);
        ss1 += __shfl_xor_sync(0xffffffffu, ss1, o);
        sd1 += __shfl_xor_sync(0xffffffffu, sd1, o);
    }
    bool ok0 = (r0 < NN), ok1 = (r0 + 8 < NN);
#pragma unroll
    for (int nt = 0; nt < 8; nt++) {
        int col = nt * 8 + 2 * tig;
        if (ok0)
            *(__half2*)(g_hh + (size_t)r0 * DD + col) =
                __floats2half2_rn(acc[nt][0], acc[nt][1]);
        if (ok1)
            *(__half2*)(g_hh + (size_t)(r0 + 8) * DD + col) =
                __floats2half2_rn(acc[nt][2], acc[nt][3]);
    }
    if (tig == 0) {
        if (ok0) { g_ssrc[r0] = ss0; g_sdst[r0] = sd0; }
        if (ok1) { g_ssrc[r0 + 8] = ss1; g_sdst[r0 + 8] = sd1; }
    }
}

// ---------------- per-dst softmax (1 exp/edge) + aggregation -------------
__global__ void __launch_bounds__(256) k_agg(float* __restrict__ yext,
                                             int is_last, int do_elu) {
    __shared__ float sp[8][CAP];
    __shared__ unsigned short ssv[8][CAP];
    int wib = threadIdx.x >> 5;
    int w = (blockIdx.x * blockDim.x + threadIdx.x) >> 5;
    int lane = threadIdx.x & 31;
    if (w >= NN) return;
    int start = g_rowptr[w], end = g_rowptr[w + 1];
    float sd = g_sdst[w];

    float z = 0.f;
    for (int j = start + lane; j < end; j += 32) {
        unsigned short s = g_srcs16[j];
        float e = g_ssrc[s] + sd;
        e = (e > 0.f) ? e : 0.2f * e;
        e = fminf(e, 60.f);
        float p = __expf(e);
        int idx = j - start;
        if (idx < CAP) { sp[wib][idx] = p; ssv[wib][idx] = s; }
        z += p;
    }
#pragma unroll
    for (int o = 16; o; o >>= 1) z += __shfl_xor_sync(0xffffffffu, z, o);
    float inv = 1.f / (z + 1e-16f);
    __syncwarp();

    int q = lane >> 3, l8 = lane & 7;
    float acc[8];
#pragma unroll
    for (int i = 0; i < 8; i++) acc[i] = 0.f;
    const uint4* h16 = (const uint4*)g_hh;
    for (int j = start + q; j < end; j += 4) {
        int idx = j - start;
        int s; float p;
        if (idx < CAP) { s = ssv[wib][idx]; p = sp[wib][idx]; }
        else {
            s = g_srcs16[j];
            float e = g_ssrc[s] + sd;
            e = (e > 0.f) ? e : 0.2f * e;
            p = __expf(fminf(e, 60.f));
        }
        float wgt = p * inv;
        uint4 hv = h16[(size_t)s * 8 + l8];
        float2 f0 = __half22float2(*reinterpret_cast<const __half2*>(&hv.x));
        float2 f1 = __half22float2(*reinterpret_cast<const __half2*>(&hv.y));
        float2 f2 = __half22float2(*reinterpret_cast<const __half2*>(&hv.z));
        float2 f3 = __half22float2(*reinterpret_cast<const __half2*>(&hv.w));
        acc[0] = fmaf(f0.x, wgt, acc[0]);
        acc[1] = fmaf(f0.y, wgt, acc[1]);
        acc[2] = fmaf(f1.x, wgt, acc[2]);
        acc[3] = fmaf(f1.y, wgt, acc[3]);
        acc[4] = fmaf(f2.x, wgt, acc[4]);
        acc[5] = fmaf(f2.y, wgt, acc[5]);
        acc[6] = fmaf(f3.x, wgt, acc[6]);
        acc[7] = fmaf(f3.y, wgt, acc[7]);
    }
#pragma unroll
    for (int i = 0; i < 8; i++) {
        acc[i] += __shfl_xor_sync(0xffffffffu, acc[i], 8);
        acc[i] += __shfl_xor_sync(0xffffffffu, acc[i], 16);
    }
    if (q == 0) {
        if (do_elu) {
#pragma unroll
            for (int i = 0; i < 8; i++)
                acc[i] = (acc[i] > 0.f) ? acc[i] : (__expf(acc[i]) - 1.f);
        }
        if (is_last) {
            float4 v0 = make_float4(acc[0], acc[1], acc[2], acc[3]);
            float4 v1 = make_float4(acc[4], acc[5], acc[6], acc[7]);
            ((float4*)yext)[(size_t)w * 16 + l8 * 2]     = v0;
            ((float4*)yext)[(size_t)w * 16 + l8 * 2 + 1] = v1;
        } else {
            ushort4 hh0, ll0, hh1, ll1;
            split_bf16(acc[0], hh0.x, ll0.x);
            split_bf16(acc[1], hh0.y, ll0.y);
            split_bf16(acc[2], hh0.z, ll0.z);
            split_bf16(acc[3], hh0.w, ll0.w);
            split_bf16(acc[4], hh1.x, ll1.x);
            split_bf16(acc[5], hh1.y, ll1.y);
            split_bf16(acc[6], hh1.z, ll1.z);
            split_bf16(acc[7], hh1.w, ll1.w);
            *(ushort4*)(g_xh + (size_t)w * DD + l8 * 8)     = hh0;
            *(ushort4*)(g_xh + (size_t)w * DD + l8 * 8 + 4) = hh1;
            *(ushort4*)(g_xl + (size_t)w * DD + l8 * 8)     = ll0;
            *(ushort4*)(g_xl + (size_t)w * DD + l8 * 8 + 4) = ll1;
        }
    }
}

// ---------------- launch ----------------
extern "C" void kernel_launch(void* const* d_in, const int* in_sizes, int n_in,
                              void* d_out, int out_size) {
    const float* feat  = (const float*)d_in[0];
    const void*  eidx  = d_in[1];
    const float* W1    = (const float*)d_in[2];
    const float* a_s1  = (const float*)d_in[3];
    const float* a_d1  = (const float*)d_in[4];
    const float* W2    = (const float*)d_in[5];
    const float* a_s2  = (const float*)d_in[6];
    const float* a_d2  = (const float*)d_in[7];
    float* out = (float*)d_out;

    int E = in_sizes[1] / 2;

    static int smem_set = 0;
    if (!smem_set) {
        cudaFuncSetAttribute(k_gemm, cudaFuncAttributeMaxDynamicSharedMemorySize, 55296);
        smem_set = 1;
    }

    const int gemm_grid = (NN + BR - 1) / BR;
    const int agg_grid  = (NN * 32 + 255) / 256;

    k_init<<<(NN * DD + 255) / 256, 256>>>((const int*)eidx, feat, W1, W2);  // 0
    k_hist<<<(E / 4 + 255) / 256, 256>>>(eidx, E);                           // 1
    k_scanA<<<NB, 256>>>();                                                  // 2
    k_scanB<<<1, 256>>>();                                                   // 3
    k_scanC<<<NB, 256>>>(E);                                                 // 4
    k_scatter<<<(E / 4 + 255) / 256, 256>>>(eidx, E);                        // 5
    k_gemm<<<gemm_grid, 256, 55296>>>(0, a_s1, a_d1);                        // 6
    k_agg<<<agg_grid, 256>>>(out, 0, 0);                                     // 7

    for (int layer = 0; layer < 2; layer++) {
        const float* as = layer ? a_s2 : a_s1;
        const float* ad = layer ? a_d2 : a_d1;
        for (int head = (layer == 0 ? 1 : 0); head < 4; head++) {
            int g = layer * 4 + head;
            int last = (layer == 1 && head == 3);
            int eol  = (head == 3);
            k_gemm<<<gemm_grid, 256, 55296>>>(g, as + head * DD, ad + head * DD);
            k_agg<<<agg_grid, 256>>>(out, last, eol);
        }
    }
}

// round 10
// speedup vs baseline: 1.0042x; 1.0042x over previous
#include <cuda_runtime.h>
#include <cuda_fp16.h>
#include <cuda_bf16.h>
#include <math.h>
#include <stdint.h>

#define NN 50000
#define EE 800000
#define DD 64
#define BR 128   // rows per GEMM block (8 warps x 16 rows)
#define CAP 96   // per-warp smem stash (max in-degree safety; Poisson(16))
#define NB ((NN + 255) / 256)   // 196 scan blocks

// ---------------- device scratch (static, no allocation) ----------------
__device__ int   g_flag;
__device__ int   g_cnt[NN];
__device__ int   g_rowptr[NN + 1];
__device__ int   g_fill[NN];
__device__ int   g_bsum[NB];
__device__ unsigned short g_srcs16[EE];
__device__ __align__(16) unsigned short g_xh[NN * DD];     // x hi (bf16 bits)
__device__ __align__(16) unsigned short g_xl[NN * DD];     // x lo (bf16 bits)
__device__ __align__(16) unsigned short g_Wh[8 * DD * DD]; // W^T hi, 8 slots
__device__ __align__(16) unsigned short g_Wl[8 * DD * DD]; // W^T lo
__device__ __align__(16) __half g_hh[NN * DD];             // per-conv h (fp16)
__device__ float g_ssrc[NN];
__device__ float g_sdst[NN];

__device__ __forceinline__ void split_bf16(float v, unsigned short& hi, unsigned short& lo) {
    __nv_bfloat16 h = __float2bfloat16(v);
    float r = v - __bfloat162float(h);
    __nv_bfloat16 l = __float2bfloat16(r);
    hi = *reinterpret_cast<unsigned short*>(&h);
    lo = *reinterpret_cast<unsigned short*>(&l);
}

// ---------------- launch 0: init (detect + zero + cvt feat + cvt W) -----
__global__ void k_init(const int* __restrict__ raw,
                       const float* __restrict__ feat,
                       const float* __restrict__ W1,
                       const float* __restrict__ W2) {
    int i = blockIdx.x * blockDim.x + threadIdx.x;
    if (i < NN * DD) split_bf16(feat[i], g_xh[i], g_xl[i]);
    if (i < NN) g_cnt[i] = 0;
    if (i < 8 * DD * DD) {
        int g = i >> 12;
        int idx = i & 4095;
        int k = idx >> 6, c = idx & 63;
        const float* W = (g < 4) ? W1 : W2;
        float v = W[(g & 3) * DD * DD + k * DD + c];
        split_bf16(v, g_Wh[g * DD * DD + c * DD + k], g_Wl[g * DD * DD + c * DD + k]);
    }
    if (blockIdx.x == 0) {
        __shared__ int ok;
        if (threadIdx.x == 0) ok = 1;
        __syncthreads();
        for (int j = threadIdx.x; j < 4096; j += blockDim.x)
            if (raw[2 * j + 1] != 0) ok = 0;
        __syncthreads();
        if (threadIdx.x == 0) g_flag = ok;
    }
}

// ---------------- histogram of dst ----------------
__global__ void k_hist(const void* __restrict__ raw, int E) {
    int base = (blockIdx.x * blockDim.x + threadIdx.x) * 4;
    if (g_flag) {
        const long long* p = (const long long*)raw + E;
#pragma unroll
        for (int u = 0; u < 4; u++) { int j = base + u; if (j < E) atomicAdd(&g_cnt[(int)p[j]], 1); }
    } else {
        const int* p = (const int*)raw + E;
#pragma unroll
        for (int u = 0; u < 4; u++) { int j = base + u; if (j < E) atomicAdd(&g_cnt[p[j]], 1); }
    }
}

// ---------------- 2-phase parallel scan ----------------
// Phase A: block-local exclusive scan into g_rowptr; block sum -> g_bsum.
__global__ void k_scanA() {
    __shared__ int sh[256];
    int t = threadIdx.x;
    int i = blockIdx.x * 256 + t;
    int v = (i < NN) ? g_cnt[i] : 0;
    sh[t] = v;
    __syncthreads();
#pragma unroll
    for (int off = 1; off < 256; off <<= 1) {
        int u = (t >= off) ? sh[t - off] : 0;
        __syncthreads();
        sh[t] += u;
        __syncthreads();
    }
    if (i < NN) g_rowptr[i] = sh[t] - v;         // local exclusive
    if (t == 255) g_bsum[blockIdx.x] = sh[255];
}

// Phase B+C fused: each block reduces bsum[0..bid) itself, then applies.
__global__ void k_scanC(int E) {
    __shared__ int wsum[8];
    __shared__ int off;
    int t = threadIdx.x;
    int partial = 0;
    for (int j = t; j < blockIdx.x; j += 256) partial += g_bsum[j];
#pragma unroll
    for (int o = 16; o; o >>= 1) partial += __shfl_xor_sync(0xffffffffu, partial, o);
    if ((t & 31) == 0) wsum[t >> 5] = partial;
    __syncthreads();
    if (t == 0) {
        int s = 0;
#pragma unroll
        for (int i = 0; i < 8; i++) s += wsum[i];
        off = s;
    }
    __syncthreads();
    int i = blockIdx.x * 256 + t;
    if (i < NN) {
        int r = g_rowptr[i] + off;
        g_rowptr[i] = r;
        g_fill[i] = r;
    }
    if (i == 0) g_rowptr[NN] = E;
}

// ---------------- scatter into CSR ----------------
__global__ void k_scatter(const void* __restrict__ raw, int E) {
    int base = (blockIdx.x * blockDim.x + threadIdx.x) * 4;
    if (g_flag) {
        const long long* p = (const long long*)raw;
#pragma unroll
        for (int u = 0; u < 4; u++) {
            int j = base + u;
            if (j < E) {
                int pos = atomicAdd(&g_fill[(int)p[E + j]], 1);
                g_srcs16[pos] = (unsigned short)(int)p[j];
            }
        }
    } else {
        const int* p = (const int*)raw;
#pragma unroll
        for (int u = 0; u < 4; u++) {
            int j = base + u;
            if (j < E) {
                int pos = atomicAdd(&g_fill[p[E + j]], 1);
                g_srcs16[pos] = (unsigned short)p[j];
            }
        }
    }
}

// ---------------- tensor-core GEMM (8 warps, dynamic smem) --------------
__global__ void __launch_bounds__(256) k_gemm(
        int g, const float* __restrict__ a_s, const float* __restrict__ a_d) {
    extern __shared__ __align__(16) char smem[];
    unsigned short (*Ah)[72] = (unsigned short(*)[72])(smem);
    unsigned short (*Al)[72] = (unsigned short(*)[72])(smem + 18432);
    unsigned short (*Bh)[72] = (unsigned short(*)[72])(smem + 36864);
    unsigned short (*Bl)[72] = (unsigned short(*)[72])(smem + 46080);
    int t = threadIdx.x;
    int rb = blockIdx.x * BR;

    for (int i = t; i < 512; i += 256) {
        int c = i >> 3, q = i & 7;
        ((uint4*)&Bh[c][0])[q] = ((const uint4*)(g_Wh + g * DD * DD + c * DD))[q];
        ((uint4*)&Bl[c][0])[q] = ((const uint4*)(g_Wl + g * DD * DD + c * DD))[q];
    }
    for (int i = t; i < 1024; i += 256) {
        int r = i >> 3, q = i & 7;
        int gr = rb + r; if (gr >= NN) gr = 0;
        ((uint4*)&Ah[r][0])[q] = ((const uint4*)(g_xh + (size_t)gr * DD))[q];
        ((uint4*)&Al[r][0])[q] = ((const uint4*)(g_xl + (size_t)gr * DD))[q];
    }
    __syncthreads();

    int lane = t & 31, wid = t >> 5;
    int gid = lane >> 2, tig = lane & 3;

    float acc[8][4];
#pragma unroll
    for (int nt = 0; nt < 8; nt++)
#pragma unroll
        for (int q = 0; q < 4; q++) acc[nt][q] = 0.f;

#pragma unroll
    for (int ks = 0; ks < 4; ks++) {
        int k0 = ks * 16 + 2 * tig;
        int r0 = wid * 16 + gid;
        uint32_t ahi[4], alo[4];
        ahi[0] = *(const uint32_t*)&Ah[r0][k0];
        ahi[1] = *(const uint32_t*)&Ah[r0 + 8][k0];
        ahi[2] = *(const uint32_t*)&Ah[r0][k0 + 8];
        ahi[3] = *(const uint32_t*)&Ah[r0 + 8][k0 + 8];
        alo[0] = *(const uint32_t*)&Al[r0][k0];
        alo[1] = *(const uint32_t*)&Al[r0 + 8][k0];
        alo[2] = *(const uint32_t*)&Al[r0][k0 + 8];
        alo[3] = *(const uint32_t*)&Al[r0 + 8][k0 + 8];
#pragma unroll
        for (int nt = 0; nt < 8; nt++) {
            int n = nt * 8 + gid;
            uint32_t bhi[2], blo[2];
            bhi[0] = *(const uint32_t*)&Bh[n][k0];
            bhi[1] = *(const uint32_t*)&Bh[n][k0 + 8];
            blo[0] = *(const uint32_t*)&Bl[n][k0];
            blo[1] = *(const uint32_t*)&Bl[n][k0 + 8];
            asm volatile(
                "mma.sync.aligned.m16n8k16.row.col.f32.bf16.bf16.f32 "
                "{%0,%1,%2,%3}, {%4,%5,%6,%7}, {%8,%9}, {%0,%1,%2,%3};"
                : "+f"(acc[nt][0]), "+f"(acc[nt][1]), "+f"(acc[nt][2]), "+f"(acc[nt][3])
                : "r"(ahi[0]), "r"(ahi[1]), "r"(ahi[2]), "r"(ahi[3]),
                  "r"(bhi[0]), "r"(bhi[1]));
            asm volatile(
                "mma.sync.aligned.m16n8k16.row.col.f32.bf16.bf16.f32 "
                "{%0,%1,%2,%3}, {%4,%5,%6,%7}, {%8,%9}, {%0,%1,%2,%3};"
                : "+f"(acc[nt][0]), "+f"(acc[nt][1]), "+f"(acc[nt][2]), "+f"(acc[nt][3])
                : "r"(ahi[0]), "r"(ahi[1]), "r"(ahi[2]), "r"(ahi[3]),
                  "r"(blo[0]), "r"(blo[1]));
            asm volatile(
                "mma.sync.aligned.m16n8k16.row.col.f32.bf16.bf16.f32 "
                "{%0,%1,%2,%3}, {%4,%5,%6,%7}, {%8,%9}, {%0,%1,%2,%3};"
                : "+f"(acc[nt][0]), "+f"(acc[nt][1]), "+f"(acc[nt][2]), "+f"(acc[nt][3])
                : "r"(alo[0]), "r"(alo[1]), "r"(alo[2]), "r"(alo[3]),
                  "r"(bhi[0]), "r"(bhi[1]));
        }
    }

    float2 asv[8], adv[8];
#pragma unroll
    for (int nt = 0; nt < 8; nt++) {
        asv[nt] = ((const float2*)a_s)[nt * 4 + tig];
        adv[nt] = ((const float2*)a_d)[nt * 4 + tig];
    }
    int r0 = rb + wid * 16 + gid;
    float ss0 = 0.f, sd0 = 0.f, ss1 = 0.f, sd1 = 0.f;
#pragma unroll
    for (int nt = 0; nt < 8; nt++) {
        ss0 = fmaf(acc[nt][0], asv[nt].x, fmaf(acc[nt][1], asv[nt].y, ss0));
        sd0 = fmaf(acc[nt][0], adv[nt].x, fmaf(acc[nt][1], adv[nt].y, sd0));
        ss1 = fmaf(acc[nt][2], asv[nt].x, fmaf(acc[nt][3], asv[nt].y, ss1));
        sd1 = fmaf(acc[nt][2], adv[nt].x, fmaf(acc[nt][3], adv[nt].y, sd1));
    }
#pragma unroll
    for (int o = 1; o <= 2; o <<= 1) {
        ss0 += __shfl_xor_sync(0xffffffffu, ss0, o);
        sd0 += __shfl_xor_sync(0xffffffffu, sd0, o);
        ss1 += __shfl_xor_sync(0xffffffffu, ss1, o);
        sd1 += __shfl_xor_sync(0xffffffffu, sd1, o);
    }
    bool ok0 = (r0 < NN), ok1 = (r0 + 8 < NN);
#pragma unroll
    for (int nt = 0; nt < 8; nt++) {
        int col = nt * 8 + 2 * tig;
        if (ok0)
            *(__half2*)(g_hh + (size_t)r0 * DD + col) =
                __floats2half2_rn(acc[nt][0], acc[nt][1]);
        if (ok1)
            *(__half2*)(g_hh + (size_t)(r0 + 8) * DD + col) =
                __floats2half2_rn(acc[nt][2], acc[nt][3]);
    }
    if (tig == 0) {
        if (ok0) { g_ssrc[r0] = ss0; g_sdst[r0] = sd0; }
        if (ok1) { g_ssrc[r0 + 8] = ss1; g_sdst[r0 + 8] = sd1; }
    }
}

// ---------------- per-dst softmax (1 exp/edge) + aggregation -------------
__global__ void __launch_bounds__(256) k_agg(float* __restrict__ yext,
                                             int is_last, int do_elu) {
    __shared__ float sp[8][CAP];
    __shared__ unsigned short ssv[8][CAP];
    int wib = threadIdx.x >> 5;
    int w = (blockIdx.x * blockDim.x + threadIdx.x) >> 5;
    int lane = threadIdx.x & 31;
    if (w >= NN) return;
    int start = g_rowptr[w], end = g_rowptr[w + 1];
    float sd = g_sdst[w];

    float z = 0.f;
    for (int j = start + lane; j < end; j += 32) {
        unsigned short s = g_srcs16[j];
        float e = g_ssrc[s] + sd;
        e = (e > 0.f) ? e : 0.2f * e;
        e = fminf(e, 60.f);
        float p = __expf(e);
        int idx = j - start;
        if (idx < CAP) { sp[wib][idx] = p; ssv[wib][idx] = s; }
        z += p;
    }
#pragma unroll
    for (int o = 16; o; o >>= 1) z += __shfl_xor_sync(0xffffffffu, z, o);
    float inv = 1.f / (z + 1e-16f);
    __syncwarp();

    int q = lane >> 3, l8 = lane & 7;
    float acc[8];
#pragma unroll
    for (int i = 0; i < 8; i++) acc[i] = 0.f;
    const uint4* h16 = (const uint4*)g_hh;
    for (int j = start + q; j < end; j += 4) {
        int idx = j - start;
        int s; float p;
        if (idx < CAP) { s = ssv[wib][idx]; p = sp[wib][idx]; }
        else {
            s = g_srcs16[j];
            float e = g_ssrc[s] + sd;
            e = (e > 0.f) ? e : 0.2f * e;
            p = __expf(fminf(e, 60.f));
        }
        float wgt = p * inv;
        uint4 hv = h16[(size_t)s * 8 + l8];
        float2 f0 = __half22float2(*reinterpret_cast<const __half2*>(&hv.x));
        float2 f1 = __half22float2(*reinterpret_cast<const __half2*>(&hv.y));
        float2 f2 = __half22float2(*reinterpret_cast<const __half2*>(&hv.z));
        float2 f3 = __half22float2(*reinterpret_cast<const __half2*>(&hv.w));
        acc[0] = fmaf(f0.x, wgt, acc[0]);
        acc[1] = fmaf(f0.y, wgt, acc[1]);
        acc[2] = fmaf(f1.x, wgt, acc[2]);
        acc[3] = fmaf(f1.y, wgt, acc[3]);
        acc[4] = fmaf(f2.x, wgt, acc[4]);
        acc[5] = fmaf(f2.y, wgt, acc[5]);
        acc[6] = fmaf(f3.x, wgt, acc[6]);
        acc[7] = fmaf(f3.y, wgt, acc[7]);
    }
#pragma unroll
    for (int i = 0; i < 8; i++) {
        acc[i] += __shfl_xor_sync(0xffffffffu, acc[i], 8);
        acc[i] += __shfl_xor_sync(0xffffffffu, acc[i], 16);
    }
    if (q == 0) {
        if (do_elu) {
#pragma unroll
            for (int i = 0; i < 8; i++)
                acc[i] = (acc[i] > 0.f) ? acc[i] : (__expf(acc[i]) - 1.f);
        }
        if (is_last) {
            float4 v0 = make_float4(acc[0], acc[1], acc[2], acc[3]);
            float4 v1 = make_float4(acc[4], acc[5], acc[6], acc[7]);
            ((float4*)yext)[(size_t)w * 16 + l8 * 2]     = v0;
            ((float4*)yext)[(size_t)w * 16 + l8 * 2 + 1] = v1;
        } else {
            ushort4 hh0, ll0, hh1, ll1;
            split_bf16(acc[0], hh0.x, ll0.x);
            split_bf16(acc[1], hh0.y, ll0.y);
            split_bf16(acc[2], hh0.z, ll0.z);
            split_bf16(acc[3], hh0.w, ll0.w);
            split_bf16(acc[4], hh1.x, ll1.x);
            split_bf16(acc[5], hh1.y, ll1.y);
            split_bf16(acc[6], hh1.z, ll1.z);
            split_bf16(acc[7], hh1.w, ll1.w);
            *(ushort4*)(g_xh + (size_t)w * DD + l8 * 8)     = hh0;
            *(ushort4*)(g_xh + (size_t)w * DD + l8 * 8 + 4) = hh1;
            *(ushort4*)(g_xl + (size_t)w * DD + l8 * 8)     = ll0;
            *(ushort4*)(g_xl + (size_t)w * DD + l8 * 8 + 4) = ll1;
        }
    }
}

// ---------------- launch ----------------
extern "C" void kernel_launch(void* const* d_in, const int* in_sizes, int n_in,
                              void* d_out, int out_size) {
    const float* feat  = (const float*)d_in[0];
    const void*  eidx  = d_in[1];
    const float* W1    = (const float*)d_in[2];
    const float* a_s1  = (const float*)d_in[3];
    const float* a_d1  = (const float*)d_in[4];
    const float* W2    = (const float*)d_in[5];
    const float* a_s2  = (const float*)d_in[6];
    const float* a_d2  = (const float*)d_in[7];
    float* out = (float*)d_out;

    int E = in_sizes[1] / 2;

    static int smem_set = 0;
    if (!smem_set) {
        cudaFuncSetAttribute(k_gemm, cudaFuncAttributeMaxDynamicSharedMemorySize, 55296);
        smem_set = 1;
    }

    const int gemm_grid = (NN + BR - 1) / BR;
    const int agg_grid  = (NN * 32 + 255) / 256;

    // R8 ordering: gemm(head0) immediately after init, CSR build after.
    k_init<<<(NN * DD + 255) / 256, 256>>>((const int*)eidx, feat, W1, W2);  // 0
    k_gemm<<<gemm_grid, 256, 55296>>>(0, a_s1, a_d1);                        // 1
    k_hist<<<(E / 4 + 255) / 256, 256>>>(eidx, E);                           // 2
    k_scanA<<<NB, 256>>>();                                                  // 3
    k_scanC<<<NB, 256>>>(E);                                                 // 4
    k_scatter<<<(E / 4 + 255) / 256, 256>>>(eidx, E);                        // 5
    k_agg<<<agg_grid, 256>>>(out, 0, 0);                                     // 6

    for (int layer = 0; layer < 2; layer++) {
        const float* as = layer ? a_s2 : a_s1;
        const float* ad = layer ? a_d2 : a_d1;
        for (int head = (layer == 0 ? 1 : 0); head < 4; head++) {
            int g = layer * 4 + head;
            int last = (layer == 1 && head == 3);
            int eol  = (head == 3);
            k_gemm<<<gemm_grid, 256, 55296>>>(g, as + head * DD, ad + head * DD);
            k_agg<<<agg_grid, 256>>>(out, last, eol);
        }
    }
}